// round 11
// baseline (speedup 1.0000x reference)
#include <cuda_runtime.h>
#include <cuda_bf16.h>
#include <cstdint>

#define BB 4
#define NN 8192
#define NPOINT 2048
#define CC 64
#define NS 32
#define NSP 33      // NSAMPLE + 1 (fps_idx prepended)
#define TOTCH 70    // 3 + 3 + 64
#define NC1 10      // grid cells per axis (cell size = radius = 0.1)
#define NCELLS 1000
#define BUFSZ 128   // per-ball candidate cap (expected ~34 hits)

// Block-role layout (producers FIRST: dispatch order => no deadlock)
#define GB_BLOCKS 4
#define FT_BLOCKS 1024                     // 4 b * 2 c-blk * 128 n-blk
#define BQ_BLOCKS 2048
#define NBLOCKS   (GB_BLOCKS + FT_BLOCKS + BQ_BLOCKS)

// Scratch (device globals — no allocations allowed)
__device__ float4 g_p4[BB * NN];        // xyz by original index (w unused)
__device__ int    g_off[BB * NCELLS];   // cell start
__device__ int    g_end[BB * NCELLS];   // cell end
__device__ float4 g_g4[BB * NN];        // cell-sorted (x,y,z, idx-bits)
__device__ float4 g_ft4[BB * NN * (CC / 4)];  // features (B,N,C) as float4

// Phase flags (self-resetting: last bq block zeroes them for graph replay)
__device__ volatile int g_flag_gb;
__device__ volatile int g_flag_ft;
__device__ int g_done;

// ---------------------------------------------------------------------------
__device__ __forceinline__ int cell_coord(float v) {
    int c = (int)(v * 10.0f);
    return c < 0 ? 0 : (c > 9 ? 9 : c);
}

#define FW 4
#define PCH 16                       // channels per pass
#define TROW 132                     // 4 balls * 33 slots

// ---------------------------------------------------------------------------
// ONE kernel, three roles. smem is a union sized by the bq role (10.6KB) so
// bq keeps 16 blocks x 4 warps = 64 warps/SM.
// ---------------------------------------------------------------------------
__global__ __launch_bounds__(128, 16) void mega_kernel(
        const float* __restrict__ xyz,
        const float* __restrict__ new_xyz,
        const float* __restrict__ f,
        const int*   __restrict__ fps_idx,
        float* __restrict__ out) {
    __shared__ union {
        int   hist[1024];                            // gb: 4KB (pad 1000->1024)
        float ft_tile[2][32][33];                    // ft: 8.4KB
        struct {
            float tile[PCH * TROW];                  // 8448B
            int   sidx[FW][NSP];                     // 528B
            float cxs[FW][3][NSP];                   // 1584B
        } bq;
    } sm;
    __shared__ int wsum[4];

    const int tid = threadIdx.x;
    const int bid = blockIdx.x;

    if (bid < GB_BLOCKS) {
        // ================= role 1: grid build (one block per batch) =========
        const int b = bid;
        const int lane = tid & 31;
        const int wid = tid >> 5;

        for (int c = tid; c < 1024; c += 128) sm.hist[c] = 0;
        __syncthreads();

        for (int p = tid; p < NN; p += 128) {
            const float x = xyz[(b * NN + p) * 3 + 0];
            const float y = xyz[(b * NN + p) * 3 + 1];
            const float z = xyz[(b * NN + p) * 3 + 2];
            g_p4[b * NN + p] = make_float4(x, y, z, 0.0f);
            const int cell =
                (cell_coord(z) * NC1 + cell_coord(y)) * NC1 + cell_coord(x);
            atomicAdd(&sm.hist[cell], 1);
        }
        __syncthreads();

        // scan: thread owns cells [8t, 8t+8)
        int run = 0;
        #pragma unroll
        for (int k = 0; k < 8; k++) run += sm.hist[tid * 8 + k];
        int sc = run;
        #pragma unroll
        for (int d = 1; d < 32; d <<= 1) {
            const int n = __shfl_up_sync(0xffffffffu, sc, d);
            if (lane >= d) sc += n;
        }
        if (lane == 31) wsum[wid] = sc;
        __syncthreads();
        int woff = 0;
        for (int ww = 0; ww < 4; ww++) if (ww < wid) woff += wsum[ww];
        int excl = woff + sc - run;
        // write offsets + convert hist to cursors
        {
            int run2 = 0;
            #pragma unroll
            for (int k = 0; k < 8; k++) {
                const int c = tid * 8 + k;
                const int h = sm.hist[c];
                const int off = excl + run2;
                run2 += h;
                if (c < NCELLS) {
                    g_off[b * NCELLS + c] = off;
                    g_end[b * NCELLS + c] = off + h;
                }
                sm.hist[c] = off;
            }
        }
        __syncthreads();

        // scatter (recompute cell from g_p4 — no cell cache needed)
        for (int p = tid; p < NN; p += 128) {
            float4 q = g_p4[b * NN + p];
            const int cell =
                (cell_coord(q.z) * NC1 + cell_coord(q.y)) * NC1 +
                cell_coord(q.x);
            const int pos = atomicAdd(&sm.hist[cell], 1);
            q.w = __int_as_float(p);
            g_g4[b * NN + pos] = q;
        }
        __threadfence();
        __syncthreads();
        if (tid == 0) atomicAdd((int*)&g_flag_gb, 1);

    } else if (bid < GB_BLOCKS + FT_BLOCKS) {
        // ================= role 2: feature transpose ========================
        const int bid2 = bid - GB_BLOCKS;
        const int b    = bid2 >> 8;            // / 256
        const int r    = bid2 & 255;
        const int c0   = (r >> 7) * 32;
        const int n0   = (r & 127) * 64;

        #pragma unroll
        for (int h = 0; h < 2; h++) {
            for (int idx = tid; idx < 256; idx += 128) {
                const int c = idx >> 3, q = idx & 7;
                const float4 v = *(const float4*)
                    &f[((size_t)(b * CC + c0 + c)) * NN + n0 + h * 32 + q * 4];
                float* tw = &sm.ft_tile[h][c][q * 4];
                tw[0] = v.x; tw[1] = v.y; tw[2] = v.z; tw[3] = v.w;
            }
        }
        __syncthreads();
        #pragma unroll
        for (int h = 0; h < 2; h++) {
            for (int idx = tid; idx < 256; idx += 128) {
                const int n = idx >> 3, c4 = idx & 7;
                float4 v;
                v.x = sm.ft_tile[h][c4 * 4 + 0][n];
                v.y = sm.ft_tile[h][c4 * 4 + 1][n];
                v.z = sm.ft_tile[h][c4 * 4 + 2][n];
                v.w = sm.ft_tile[h][c4 * 4 + 3][n];
                *(float4*)((float*)g_ft4 +
                    ((size_t)(b * NN + n0 + h * 32 + n)) * CC + c0 + c4 * 4) = v;
            }
        }
        __threadfence();
        __syncthreads();
        if (tid == 0) atomicAdd((int*)&g_flag_ft, 1);

    } else {
        // ================= role 3: ball query + gather (R7 code) ============
        const int gbid = bid - GB_BLOCKS - FT_BLOCKS;
        const int lane = tid & 31;
        const int wid  = tid >> 5;
        const int w = gbid * FW + wid;
        const int b = w / NPOINT;
        const int j0 = (gbid * FW) % NPOINT;

        const float cx = __ldg(&new_xyz[w * 3 + 0]);
        const float cy = __ldg(&new_xyz[w * 3 + 1]);
        const float cz = __ldg(&new_xyz[w * 3 + 2]);
        const float r2 = __fmul_rn(0.1f, 0.1f);

        unsigned short* buf = (unsigned short*)sm.bq.tile + wid * BUFSZ;

        // ---- wait for grid build ----
        if (tid == 0) {
            while (g_flag_gb != GB_BLOCKS) __nanosleep(128);
            __threadfence();
        }
        __syncthreads();

        // ---- Phase A: collection ----
        const int icx = cell_coord(cx), icy = cell_coord(cy),
                  icz = cell_coord(cz);
        const int x0 = icx > 0 ? icx - 1 : 0, x1 = icx < 9 ? icx + 1 : 9;
        const int y0 = icy > 0 ? icy - 1 : 0, y1 = icy < 9 ? icy + 1 : 9;
        const int z0 = icz > 0 ? icz - 1 : 0, z1 = icz < 9 ? icz + 1 : 9;
        const int ny = y1 - y0 + 1;
        const int nrows = (z1 - z0 + 1) * ny;

        int mys = 0, mye = 0;
        if (lane < nrows) {
            const int zz = z0 + lane / ny;
            const int yy = y0 + lane % ny;
            const int rowbase = b * NCELLS + (zz * NC1 + yy) * NC1;
            mys = g_off[rowbase + x0];
            mye = g_end[rowbase + x1];
        }

        const unsigned below = (1u << lane) - 1u;
        int cnt = 0;

        for (int r = 0; r < nrows; r++) {
            const int start = __shfl_sync(0xffffffffu, mys, r);
            const int end   = __shfl_sync(0xffffffffu, mye, r);
            for (int k = start; k < end; k += 32) {
                const int kk = k + lane;
                bool valid = false;
                int pi = 0;
                if (kk < end) {
                    const float4 p = g_g4[b * NN + kk];
                    const float dx = __fsub_rn(cx, p.x);
                    const float dy = __fsub_rn(cy, p.y);
                    const float dz = __fsub_rn(cz, p.z);
                    const float d2 = __fadd_rn(
                        __fadd_rn(__fmul_rn(dx, dx), __fmul_rn(dy, dy)),
                        __fmul_rn(dz, dz));
                    valid = d2 < r2;
                    pi = __float_as_int(p.w);
                }
                const unsigned m = __ballot_sync(0xffffffffu, valid);
                if (valid) {
                    const int pos = cnt + __popc(m & below);
                    if (pos < BUFSZ) buf[pos] = (unsigned short)pi;
                }
                cnt += __popc(m);
            }
        }
        if (cnt > BUFSZ) cnt = BUFSZ;
        __syncwarp();

        // rank-select smallest NS (== scan-order semantics)
        int vmin = 0x7fffffff;
        for (int t = lane; t < cnt; t += 32) {
            const int v = buf[t];
            int rank = 0;
            for (int k = 0; k < cnt; k++) rank += (buf[k] < v);
            if (rank < NS) sm.bq.sidx[wid][1 + rank] = v;
            if (v < vmin) vmin = v;
        }
        #pragma unroll
        for (int d = 16; d > 0; d >>= 1) {
            const int o = __shfl_xor_sync(0xffffffffu, vmin, d);
            if (o < vmin) vmin = o;
        }
        const int pad = (cnt > 0) ? vmin : 0;
        if (lane < NS && lane >= cnt) sm.bq.sidx[wid][1 + lane] = pad;
        if (lane == 0) sm.bq.sidx[wid][0] = fps_idx[w];
        __syncwarp();

        // centered xyz into smem
        {
            const int i = sm.bq.sidx[wid][lane];
            const float4 p = g_p4[b * NN + i];
            sm.bq.cxs[wid][0][lane] = __fsub_rn(p.x, cx);
            sm.bq.cxs[wid][1][lane] = __fsub_rn(p.y, cy);
            sm.bq.cxs[wid][2][lane] = __fsub_rn(p.z, cz);
            if (lane == 0) {
                const int i32 = sm.bq.sidx[wid][32];
                const float4 q = g_p4[b * NN + i32];
                sm.bq.cxs[wid][0][32] = __fsub_rn(q.x, cx);
                sm.bq.cxs[wid][1][32] = __fsub_rn(q.y, cy);
                sm.bq.cxs[wid][2][32] = __fsub_rn(q.z, cz);
            }
        }
        __syncthreads();

        // ---- Phase B ----
        const size_t chstr = (size_t)NPOINT * NSP;
        float* __restrict__ outb0 =
            out + ((size_t)b * TOTCH * NPOINT + j0) * NSP;

        #pragma unroll
        for (int k = 0; k < 6; k++) {
            const int k3 = (k < 3) ? k : k - 3;
            float* __restrict__ dst = outb0 + (size_t)k * chstr;
            {
                const int w4 = (tid * 993) >> 15;     // tid / 33
                const int s  = tid - w4 * 33;
                dst[tid] = sm.bq.cxs[w4][k3][s];
            }
            if (tid < 4) dst[128 + tid] = sm.bq.cxs[3][k3][29 + tid];
        }

        // ---- wait for feature transpose (overlapped past the xyz part) ----
        if (tid == 0) {
            while (g_flag_ft != FT_BLOCKS) __nanosleep(128);
            __threadfence();
        }
        __syncthreads();

        const int c4 = lane & 3;
        const int ls = lane >> 2;
        #pragma unroll
        for (int p = 0; p < 4; p++) {
            const float4* __restrict__ ftb =
                g_ft4 + (size_t)(b * NN) * 16 + p * 4 + c4;
            #pragma unroll
            for (int s0 = 0; s0 < 32; s0 += 8) {
                const int s = s0 + ls;
                const int i = sm.bq.sidx[wid][s];
                const float4 v = ftb[(size_t)i * 16];
                float* tw = &sm.bq.tile[(c4 * 4) * TROW + wid * 33 + s];
                tw[0 * TROW] = v.x; tw[1 * TROW] = v.y;
                tw[2 * TROW] = v.z; tw[3 * TROW] = v.w;
            }
            if (lane < 4) {   // s = 32
                const int i = sm.bq.sidx[wid][32];
                const float4 v = ftb[(size_t)i * 16];
                float* tw = &sm.bq.tile[(lane * 4) * TROW + wid * 33 + 32];
                tw[0 * TROW] = v.x; tw[1 * TROW] = v.y;
                tw[2 * TROW] = v.z; tw[3 * TROW] = v.w;
            }
            __syncthreads();

            for (int e = tid; e < PCH * 33; e += FW * 32) {
                const int ch = (e * 993) >> 15;        // e / 33
                const int q  = e - ch * 33;
                const float4 v = *(const float4*)&sm.bq.tile[ch * TROW + q * 4];
                *(float4*)(outb0 + (size_t)(6 + p * PCH + ch) * chstr + q * 4)
                    = v;
            }
            __syncthreads();
        }

        // ---- flag self-reset for graph replay (last bq block) ----
        __threadfence();
        if (tid == 0) {
            if (atomicAdd(&g_done, 1) == BQ_BLOCKS - 1) {
                g_flag_gb = 0;
                g_flag_ft = 0;
                __threadfence();
                g_done = 0;
            }
        }
    }
}

// ---------------------------------------------------------------------------
extern "C" void kernel_launch(void* const* d_in, const int* in_sizes, int n_in,
                              void* d_out, int out_size) {
    const float* xyz      = (const float*)d_in[0];   // (B, N, 3)
    const float* new_xyz  = (const float*)d_in[1];   // (B, NPOINT, 3)
    const float* features = (const float*)d_in[2];   // (B, C, N)
    const int*   fps_idx  = (const int*)d_in[3];     // (B, NPOINT)
    float* out = (float*)d_out;

    mega_kernel<<<NBLOCKS, 128>>>(xyz, new_xyz, features, fps_idx, out);
}

// round 13
// speedup vs baseline: 1.4954x; 1.4954x over previous
#include <cuda_runtime.h>
#include <cuda_bf16.h>
#include <cstdint>

#define BB 4
#define NN 8192
#define NPOINT 2048
#define CC 64
#define NS 32
#define NSP 33      // NSAMPLE + 1 (fps_idx prepended)
#define TOTCH 70    // 3 + 3 + 64
#define NC1 10      // grid cells per axis (cell size = radius = 0.1)
#define NCELLS 1000
#define BUFSZ 128   // per-ball candidate cap (expected ~34 hits)

// Scratch (device globals — no allocations allowed)
__device__ float4 g_p4[BB * NN];        // xyz by original index (w unused)
__device__ int    g_off[BB * NCELLS];   // cell start
__device__ int    g_end[BB * NCELLS];   // cell end
__device__ float4 g_g4[BB * NN];        // cell-sorted (x,y,z, idx-bits)
__device__ float4 g_ft4[BB * NN * (CC / 4)];  // features (B,N,C) as float4

// ---------------------------------------------------------------------------
__device__ __forceinline__ int cell_coord(float v) {
    int c = (int)(v * 10.0f);
    return c < 0 ? 0 : (c > 9 ? 9 : c);
}

// ---------------------------------------------------------------------------
// Kernel 1 (fused preprocessing): blocks 0..3 build the spatial grid (one
// 1024-thread block per batch); blocks 4..515 transpose features.
// ---------------------------------------------------------------------------
#define GB_BLOCKS BB                         // 4
#define FT_BLOCKS (BB * (CC / 32) * (NN / 128))   // 512

__global__ __launch_bounds__(1024) void pre_kernel(
        const float* __restrict__ f,
        const float* __restrict__ xyz) {
    __shared__ union {
        float tile[4][32][33];                           // transpose: 16.9KB
        struct {                                         // grid build: 20.2KB
            unsigned short cell16[NN];
            int hist[NCELLS];
            int wsum[32];
        } gb;
    } sm;

    const int t = threadIdx.x;

    if (blockIdx.x < GB_BLOCKS) {
        // ================= grid build (one block per batch) =================
        const int b = blockIdx.x;
        const int lane = t & 31;
        const int wid = t >> 5;

        if (t < NCELLS) sm.gb.hist[t] = 0;
        __syncthreads();

        for (int p = t; p < NN; p += 1024) {
            const float x = xyz[(b * NN + p) * 3 + 0];
            const float y = xyz[(b * NN + p) * 3 + 1];
            const float z = xyz[(b * NN + p) * 3 + 2];
            g_p4[b * NN + p] = make_float4(x, y, z, 0.0f);
            const int cell =
                (cell_coord(z) * NC1 + cell_coord(y)) * NC1 + cell_coord(x);
            sm.gb.cell16[p] = (unsigned short)cell;
            atomicAdd(&sm.gb.hist[cell], 1);
        }
        __syncthreads();

        const int orig = (t < NCELLS) ? sm.gb.hist[t] : 0;
        int v = orig;
        #pragma unroll
        for (int d = 1; d < 32; d <<= 1) {
            const int n = __shfl_up_sync(0xffffffffu, v, d);
            if (lane >= d) v += n;
        }
        if (lane == 31) sm.gb.wsum[wid] = v;
        __syncthreads();
        if (wid == 0) {
            int s = sm.gb.wsum[lane];
            #pragma unroll
            for (int d = 1; d < 32; d <<= 1) {
                const int n = __shfl_up_sync(0xffffffffu, s, d);
                if (lane >= d) s += n;
            }
            sm.gb.wsum[lane] = s;
        }
        __syncthreads();
        const int excl = v - orig + (wid > 0 ? sm.gb.wsum[wid - 1] : 0);
        if (t < NCELLS) {
            g_off[b * NCELLS + t] = excl;
            g_end[b * NCELLS + t] = excl + orig;
        }
        __syncthreads();
        if (t < NCELLS) sm.gb.hist[t] = excl;    // scatter cursors
        __syncthreads();

        for (int p = t; p < NN; p += 1024) {
            const int cell = sm.gb.cell16[p];
            const int pos = atomicAdd(&sm.gb.hist[cell], 1);
            float4 q = g_p4[b * NN + p];
            q.w = __int_as_float(p);
            g_g4[b * NN + pos] = q;
        }
    } else {
        // ================= feature transpose =================
        const int bid2 = blockIdx.x - GB_BLOCKS;
        const int b    = bid2 >> 7;            // / 128
        const int r    = bid2 & 127;
        const int c0   = (r >> 6) * 32;        // cblk in {0,1}
        const int n0   = (r & 63) * 128;       // nblk in 0..63

        const int h  = t >> 8;                 // 0..3 (sub-tile)
        const int tt = t & 255;

        {
            const int c = tt >> 3, q = tt & 7;
            const float4 v = *(const float4*)
                &f[((size_t)(b * CC + c0 + c)) * NN + n0 + h * 32 + q * 4];
            float* tw = &sm.tile[h][c][q * 4];
            tw[0] = v.x; tw[1] = v.y; tw[2] = v.z; tw[3] = v.w;
        }
        __syncthreads();
        {
            const int n = tt >> 3, c4 = tt & 7;
            float4 v;
            v.x = sm.tile[h][c4 * 4 + 0][n];
            v.y = sm.tile[h][c4 * 4 + 1][n];
            v.z = sm.tile[h][c4 * 4 + 2][n];
            v.w = sm.tile[h][c4 * 4 + 3][n];
            *(float4*)((float*)g_ft4 +
                ((size_t)(b * NN + n0 + h * 32 + n)) * CC + c0 + c4 * 4) = v;
        }
    }
}

// ---------------------------------------------------------------------------
// Kernel 2: fused ball-query + gather. Block = 4 warps = 4 ADJACENT balls.
// Candidate buffer holds full float4 (coords + idx-bits) so centered xyz is
// produced straight from registers during rank-selection — no scattered
// g_p4 reloads.
// ---------------------------------------------------------------------------
#define FW 4
#define PCH 16                       // channels per pass
#define TROW 132                     // 4 balls * 33 slots

__global__ __launch_bounds__(FW * 32, 16) void bq_gather_kernel(
        const float* __restrict__ new_xyz,
        const int* __restrict__ fps_idx,
        float* __restrict__ out) {
    __shared__ float s_tile[PCH * TROW];   // [ch][132]; head aliased as buf
    __shared__ int   s_sidx[FW][NSP];
    __shared__ float s_cxs[FW][3][NSP];

    const int tid  = threadIdx.x;
    const int lane = tid & 31;
    const int wid  = tid >> 5;
    const int w = blockIdx.x * FW + wid;
    const int b = w / NPOINT;
    const int j0 = (blockIdx.x * FW) % NPOINT;

    const float cx = __ldg(&new_xyz[w * 3 + 0]);
    const float cy = __ldg(&new_xyz[w * 3 + 1]);
    const float cz = __ldg(&new_xyz[w * 3 + 2]);
    const float r2 = __fmul_rn(0.1f, 0.1f);

    // per-warp float4 candidate buffer aliases the tile (2KB per warp)
    float4* buf4 = (float4*)s_tile + wid * BUFSZ;

    // ---- Phase A: collection ----
    const int icx = cell_coord(cx), icy = cell_coord(cy), icz = cell_coord(cz);
    const int x0 = icx > 0 ? icx - 1 : 0, x1 = icx < 9 ? icx + 1 : 9;
    const int y0 = icy > 0 ? icy - 1 : 0, y1 = icy < 9 ? icy + 1 : 9;
    const int z0 = icz > 0 ? icz - 1 : 0, z1 = icz < 9 ? icz + 1 : 9;
    const int ny = y1 - y0 + 1;
    const int nrows = (z1 - z0 + 1) * ny;

    int mys = 0, mye = 0;
    if (lane < nrows) {
        const int zz = z0 + lane / ny;
        const int yy = y0 + lane % ny;
        const int rowbase = b * NCELLS + (zz * NC1 + yy) * NC1;
        mys = g_off[rowbase + x0];
        mye = g_end[rowbase + x1];
    }

    const unsigned below = (1u << lane) - 1u;
    int cnt = 0;

    for (int r = 0; r < nrows; r++) {
        const int start = __shfl_sync(0xffffffffu, mys, r);
        const int end   = __shfl_sync(0xffffffffu, mye, r);
        for (int k = start; k < end; k += 32) {
            const int kk = k + lane;
            bool valid = false;
            float4 p;
            if (kk < end) {
                p = g_g4[b * NN + kk];
                const float dx = __fsub_rn(cx, p.x);
                const float dy = __fsub_rn(cy, p.y);
                const float dz = __fsub_rn(cz, p.z);
                const float d2 = __fadd_rn(
                    __fadd_rn(__fmul_rn(dx, dx), __fmul_rn(dy, dy)),
                    __fmul_rn(dz, dz));
                valid = d2 < r2;
            }
            const unsigned m = __ballot_sync(0xffffffffu, valid);
            if (valid) {
                const int pos = cnt + __popc(m & below);
                if (pos < BUFSZ) buf4[pos] = p;   // coords + idx-bits
            }
            cnt += __popc(m);
        }
    }
    if (cnt > BUFSZ) cnt = BUFSZ;
    __syncwarp();

    // ---- rank-select smallest NS; write sidx + centered xyz from regs ----
    int   vmin = 0x7fffffff;
    float vmx = 0.f, vmy = 0.f, vmz = 0.f;
    for (int t = lane; t < cnt; t += 32) {
        const float4 q = buf4[t];
        const int v = __float_as_int(q.w);
        int rank = 0;
        for (int k = 0; k < cnt; k++)
            rank += (__float_as_int(buf4[k].w) < v);
        if (rank < NS) {
            s_sidx[wid][1 + rank] = v;
            s_cxs[wid][0][1 + rank] = __fsub_rn(q.x, cx);
            s_cxs[wid][1][1 + rank] = __fsub_rn(q.y, cy);
            s_cxs[wid][2][1 + rank] = __fsub_rn(q.z, cz);
        }
        if (v < vmin) { vmin = v; vmx = q.x; vmy = q.y; vmz = q.z; }
    }
    #pragma unroll
    for (int d = 16; d > 0; d >>= 1) {
        const int   ov = __shfl_xor_sync(0xffffffffu, vmin, d);
        const float ox = __shfl_xor_sync(0xffffffffu, vmx, d);
        const float oy = __shfl_xor_sync(0xffffffffu, vmy, d);
        const float oz = __shfl_xor_sync(0xffffffffu, vmz, d);
        if (ov < vmin) { vmin = ov; vmx = ox; vmy = oy; vmz = oz; }
    }
    int   pad = vmin;
    if (cnt == 0) {                       // empty ball: pad = point 0
        pad = 0;
        const float4 z4 = g_p4[b * NN];
        vmx = z4.x; vmy = z4.y; vmz = z4.z;
    }
    if (lane < NS && lane >= cnt) {
        s_sidx[wid][1 + lane] = pad;
        s_cxs[wid][0][1 + lane] = __fsub_rn(vmx, cx);
        s_cxs[wid][1][1 + lane] = __fsub_rn(vmy, cy);
        s_cxs[wid][2][1 + lane] = __fsub_rn(vmz, cz);
    }
    if (lane == 0) {                      // slot 0: fps point
        const int i = fps_idx[w];
        s_sidx[wid][0] = i;
        const float4 q = g_p4[b * NN + i];
        s_cxs[wid][0][0] = __fsub_rn(q.x, cx);
        s_cxs[wid][1][0] = __fsub_rn(q.y, cy);
        s_cxs[wid][2][0] = __fsub_rn(q.z, cz);
    }
    __syncthreads();

    // ---- Phase B ----
    const size_t chstr = (size_t)NPOINT * NSP;
    float* __restrict__ outb0 =
        out + ((size_t)b * TOTCH * NPOINT + j0) * NSP;

    #pragma unroll
    for (int k = 0; k < 6; k++) {
        const int k3 = (k < 3) ? k : k - 3;
        float* __restrict__ dst = outb0 + (size_t)k * chstr;
        {
            const int w4 = (tid * 993) >> 15;     // tid / 33
            const int s  = tid - w4 * 33;
            dst[tid] = s_cxs[w4][k3][s];
        }
        if (tid < 4) dst[128 + tid] = s_cxs[3][k3][29 + tid];
    }

    const int c4 = lane & 3;        // float4 id within pass (4 channels)
    const int ls = lane >> 2;       // 8 s values per staging iter
    #pragma unroll
    for (int p = 0; p < 4; p++) {
        const float4* __restrict__ ftb =
            g_ft4 + (size_t)(b * NN) * 16 + p * 4 + c4;
        #pragma unroll
        for (int s0 = 0; s0 < 32; s0 += 8) {
            const int s = s0 + ls;
            const int i = s_sidx[wid][s];
            const float4 v = ftb[(size_t)i * 16];
            float* tw = &s_tile[(c4 * 4) * TROW + wid * 33 + s];
            tw[0 * TROW] = v.x; tw[1 * TROW] = v.y;
            tw[2 * TROW] = v.z; tw[3 * TROW] = v.w;
        }
        if (lane < 4) {   // s = 32
            const int i = s_sidx[wid][32];
            const float4 v = ftb[(size_t)i * 16];   // c4 = lane
            float* tw = &s_tile[(lane * 4) * TROW + wid * 33 + 32];
            tw[0 * TROW] = v.x; tw[1 * TROW] = v.y;
            tw[2 * TROW] = v.z; tw[3 * TROW] = v.w;
        }
        __syncthreads();

        for (int e = tid; e < PCH * 33; e += FW * 32) {
            const int ch = (e * 993) >> 15;        // e / 33
            const int q  = e - ch * 33;
            const float4 v = *(const float4*)&s_tile[ch * TROW + q * 4];
            *(float4*)(outb0 + (size_t)(6 + p * PCH + ch) * chstr + q * 4) = v;
        }
        __syncthreads();
    }
}

// ---------------------------------------------------------------------------
extern "C" void kernel_launch(void* const* d_in, const int* in_sizes, int n_in,
                              void* d_out, int out_size) {
    const float* xyz      = (const float*)d_in[0];   // (B, N, 3)
    const float* new_xyz  = (const float*)d_in[1];   // (B, NPOINT, 3)
    const float* features = (const float*)d_in[2];   // (B, C, N)
    const int*   fps_idx  = (const int*)d_in[3];     // (B, NPOINT)
    float* out = (float*)d_out;

    pre_kernel<<<GB_BLOCKS + FT_BLOCKS, 1024>>>(features, xyz);
    {
        const int blocks = (BB * NPOINT) / FW;   // 2048
        bq_gather_kernel<<<blocks, FW * 32>>>(new_xyz, fps_idx, out);
    }
}

// round 17
// speedup vs baseline: 1.5544x; 1.0394x over previous
#include <cuda_runtime.h>
#include <cuda_bf16.h>
#include <cstdint>

#define BB 4
#define NN 8192
#define NPOINT 2048
#define CC 64
#define NS 32
#define NSP 33      // NSAMPLE + 1 (fps_idx prepended)
#define TOTCH 70    // 3 + 3 + 64
#define NC1 10      // grid cells per axis (cell size = radius = 0.1)
#define NCELLS 1000
#define BUFSZ 128   // per-ball candidate cap (expected ~34 hits)

// Scratch (device globals — no allocations allowed)
__device__ float4 g_p4[BB * NN];        // xyz by original index (w unused)
__device__ int    g_off[BB * NCELLS];   // cell start
__device__ int    g_end[BB * NCELLS];   // cell end
__device__ float4 g_g4[BB * NN];        // cell-sorted (x,y,z, idx-bits)
__device__ float4 g_ft4[BB * NN * (CC / 4)];  // features (B,N,C) as float4

// ---------------------------------------------------------------------------
__device__ __forceinline__ int cell_coord(float v) {
    int c = (int)(v * 10.0f);
    return c < 0 ? 0 : (c > 9 ? 9 : c);
}

// ---------------------------------------------------------------------------
// Kernel 1 (fused preprocessing): blocks 0..3 build the spatial grid (one
// 1024-thread block per batch); blocks 4..515 transpose features.
// Ends with a PDL trigger so the dependent bq launch can dispatch early.
// ---------------------------------------------------------------------------
#define GB_BLOCKS BB                         // 4
#define FT_BLOCKS (BB * (CC / 32) * (NN / 128))   // 512

__global__ __launch_bounds__(1024) void pre_kernel(
        const float* __restrict__ f,
        const float* __restrict__ xyz) {
    __shared__ union {
        float tile[4][32][33];                           // transpose: 16.9KB
        struct {                                         // grid build: 20.2KB
            unsigned short cell16[NN];
            int hist[NCELLS];
            int wsum[32];
        } gb;
    } sm;

    const int t = threadIdx.x;

    if (blockIdx.x < GB_BLOCKS) {
        // ================= grid build (one block per batch) =================
        const int b = blockIdx.x;
        const int lane = t & 31;
        const int wid = t >> 5;

        if (t < NCELLS) sm.gb.hist[t] = 0;
        __syncthreads();

        for (int p = t; p < NN; p += 1024) {
            const float x = xyz[(b * NN + p) * 3 + 0];
            const float y = xyz[(b * NN + p) * 3 + 1];
            const float z = xyz[(b * NN + p) * 3 + 2];
            g_p4[b * NN + p] = make_float4(x, y, z, 0.0f);
            const int cell =
                (cell_coord(z) * NC1 + cell_coord(y)) * NC1 + cell_coord(x);
            sm.gb.cell16[p] = (unsigned short)cell;
            atomicAdd(&sm.gb.hist[cell], 1);
        }
        __syncthreads();

        const int orig = (t < NCELLS) ? sm.gb.hist[t] : 0;
        int v = orig;
        #pragma unroll
        for (int d = 1; d < 32; d <<= 1) {
            const int n = __shfl_up_sync(0xffffffffu, v, d);
            if (lane >= d) v += n;
        }
        if (lane == 31) sm.gb.wsum[wid] = v;
        __syncthreads();
        if (wid == 0) {
            int s = sm.gb.wsum[lane];
            #pragma unroll
            for (int d = 1; d < 32; d <<= 1) {
                const int n = __shfl_up_sync(0xffffffffu, s, d);
                if (lane >= d) s += n;
            }
            sm.gb.wsum[lane] = s;
        }
        __syncthreads();
        const int excl = v - orig + (wid > 0 ? sm.gb.wsum[wid - 1] : 0);
        if (t < NCELLS) {
            g_off[b * NCELLS + t] = excl;
            g_end[b * NCELLS + t] = excl + orig;
        }
        __syncthreads();
        if (t < NCELLS) sm.gb.hist[t] = excl;    // scatter cursors
        __syncthreads();

        for (int p = t; p < NN; p += 1024) {
            const int cell = sm.gb.cell16[p];
            const int pos = atomicAdd(&sm.gb.hist[cell], 1);
            float4 q = g_p4[b * NN + p];
            q.w = __int_as_float(p);
            g_g4[b * NN + pos] = q;
        }
    } else {
        // ================= feature transpose =================
        const int bid2 = blockIdx.x - GB_BLOCKS;
        const int b    = bid2 >> 7;            // / 128
        const int r    = bid2 & 127;
        const int c0   = (r >> 6) * 32;        // cblk in {0,1}
        const int n0   = (r & 63) * 128;       // nblk in 0..63

        const int h  = t >> 8;                 // 0..3 (sub-tile)
        const int tt = t & 255;

        {
            const int c = tt >> 3, q = tt & 7;
            const float4 v = *(const float4*)
                &f[((size_t)(b * CC + c0 + c)) * NN + n0 + h * 32 + q * 4];
            float* tw = &sm.tile[h][c][q * 4];
            tw[0] = v.x; tw[1] = v.y; tw[2] = v.z; tw[3] = v.w;
        }
        __syncthreads();
        {
            const int n = tt >> 3, c4 = tt & 7;
            float4 v;
            v.x = sm.tile[h][c4 * 4 + 0][n];
            v.y = sm.tile[h][c4 * 4 + 1][n];
            v.z = sm.tile[h][c4 * 4 + 2][n];
            v.w = sm.tile[h][c4 * 4 + 3][n];
            *(float4*)((float*)g_ft4 +
                ((size_t)(b * NN + n0 + h * 32 + n)) * CC + c0 + c4 * 4) = v;
        }
    }

    // PDL: all prior writes are visible to the dependent grid's
    // cudaGridDependencySynchronize().
    cudaTriggerProgrammaticLaunchCompletion();
}

// ---------------------------------------------------------------------------
// Kernel 2: fused ball-query + gather (byte-identical logic to measured-best
// R10 version, plus a PDL preamble: independent-input loads happen before
// cudaGridDependencySynchronize, grid/feature reads after).
// ---------------------------------------------------------------------------
#define FW 4
#define PCH 16                       // channels per pass
#define TROW 132                     // 4 balls * 33 slots

__global__ __launch_bounds__(FW * 32, 16) void bq_gather_kernel(
        const float* __restrict__ new_xyz,
        const int* __restrict__ fps_idx,
        float* __restrict__ out) {
    __shared__ float s_tile[PCH * TROW];   // [ch][132]; head aliased as buf
    __shared__ int   s_sidx[FW][NSP];
    __shared__ float s_cxs[FW][3][NSP];

    const int tid  = threadIdx.x;
    const int lane = tid & 31;
    const int wid  = tid >> 5;
    const int w = blockIdx.x * FW + wid;
    const int b = w / NPOINT;
    const int j0 = (blockIdx.x * FW) % NPOINT;

    // ---- PDL preamble: loads of kernel INPUTS (independent of pre) ----
    const float cx = __ldg(&new_xyz[w * 3 + 0]);
    const float cy = __ldg(&new_xyz[w * 3 + 1]);
    const float cz = __ldg(&new_xyz[w * 3 + 2]);
    const int   fpi = __ldg(&fps_idx[w]);
    const float r2 = __fmul_rn(0.1f, 0.1f);

    const int icx = cell_coord(cx), icy = cell_coord(cy), icz = cell_coord(cz);
    const int x0 = icx > 0 ? icx - 1 : 0, x1 = icx < 9 ? icx + 1 : 9;
    const int y0 = icy > 0 ? icy - 1 : 0, y1 = icy < 9 ? icy + 1 : 9;
    const int z0 = icz > 0 ? icz - 1 : 0, z1 = icz < 9 ? icz + 1 : 9;
    const int ny = y1 - y0 + 1;
    const int nrows = (z1 - z0 + 1) * ny;

    // ---- wait for pre_kernel's writes to be visible ----
    cudaGridDependencySynchronize();

    unsigned short* buf = (unsigned short*)s_tile + wid * BUFSZ;

    // ---- Phase A: collection ----
    int mys = 0, mye = 0;
    if (lane < nrows) {
        const int zz = z0 + lane / ny;
        const int yy = y0 + lane % ny;
        const int rowbase = b * NCELLS + (zz * NC1 + yy) * NC1;
        mys = g_off[rowbase + x0];
        mye = g_end[rowbase + x1];
    }

    const unsigned below = (1u << lane) - 1u;
    int cnt = 0;

    for (int r = 0; r < nrows; r++) {
        const int start = __shfl_sync(0xffffffffu, mys, r);
        const int end   = __shfl_sync(0xffffffffu, mye, r);
        for (int k = start; k < end; k += 32) {
            const int kk = k + lane;
            bool valid = false;
            int pi = 0;
            if (kk < end) {
                const float4 p = g_g4[b * NN + kk];
                const float dx = __fsub_rn(cx, p.x);
                const float dy = __fsub_rn(cy, p.y);
                const float dz = __fsub_rn(cz, p.z);
                const float d2 = __fadd_rn(
                    __fadd_rn(__fmul_rn(dx, dx), __fmul_rn(dy, dy)),
                    __fmul_rn(dz, dz));
                valid = d2 < r2;
                pi = __float_as_int(p.w);
            }
            const unsigned m = __ballot_sync(0xffffffffu, valid);
            if (valid) {
                const int pos = cnt + __popc(m & below);
                if (pos < BUFSZ) buf[pos] = (unsigned short)pi;
            }
            cnt += __popc(m);
        }
    }
    if (cnt > BUFSZ) cnt = BUFSZ;
    __syncwarp();

    // rank-select smallest NS into sidx[1..NS] (== scan-order semantics)
    int vmin = 0x7fffffff;
    for (int t = lane; t < cnt; t += 32) {
        const int v = buf[t];
        int rank = 0;
        for (int k = 0; k < cnt; k++) rank += (buf[k] < v);
        if (rank < NS) s_sidx[wid][1 + rank] = v;
        if (v < vmin) vmin = v;
    }
    #pragma unroll
    for (int d = 16; d > 0; d >>= 1) {
        const int o = __shfl_xor_sync(0xffffffffu, vmin, d);
        if (o < vmin) vmin = o;
    }
    const int pad = (cnt > 0) ? vmin : 0;
    if (lane < NS && lane >= cnt) s_sidx[wid][1 + lane] = pad;
    if (lane == 0) s_sidx[wid][0] = fpi;
    __syncwarp();

    // centered xyz into smem
    {
        const int i = s_sidx[wid][lane];
        const float4 p = g_p4[b * NN + i];
        s_cxs[wid][0][lane] = __fsub_rn(p.x, cx);
        s_cxs[wid][1][lane] = __fsub_rn(p.y, cy);
        s_cxs[wid][2][lane] = __fsub_rn(p.z, cz);
        if (lane == 0) {
            const int i32 = s_sidx[wid][32];
            const float4 q = g_p4[b * NN + i32];
            s_cxs[wid][0][32] = __fsub_rn(q.x, cx);
            s_cxs[wid][1][32] = __fsub_rn(q.y, cy);
            s_cxs[wid][2][32] = __fsub_rn(q.z, cz);
        }
    }
    __syncthreads();

    // ---- Phase B ----
    const size_t chstr = (size_t)NPOINT * NSP;
    float* __restrict__ outb0 =
        out + ((size_t)b * TOTCH * NPOINT + j0) * NSP;

    #pragma unroll
    for (int k = 0; k < 6; k++) {
        const int k3 = (k < 3) ? k : k - 3;
        float* __restrict__ dst = outb0 + (size_t)k * chstr;
        {
            const int w4 = (tid * 993) >> 15;     // tid / 33
            const int s  = tid - w4 * 33;
            dst[tid] = s_cxs[w4][k3][s];
        }
        if (tid < 4) dst[128 + tid] = s_cxs[3][k3][29 + tid];
    }

    const int c4 = lane & 3;        // float4 id within pass (4 channels)
    const int ls = lane >> 2;       // 8 s values per staging iter
    #pragma unroll
    for (int p = 0; p < 4; p++) {
        const float4* __restrict__ ftb =
            g_ft4 + (size_t)(b * NN) * 16 + p * 4 + c4;
        #pragma unroll
        for (int s0 = 0; s0 < 32; s0 += 8) {
            const int s = s0 + ls;
            const int i = s_sidx[wid][s];
            const float4 v = ftb[(size_t)i * 16];
            float* tw = &s_tile[(c4 * 4) * TROW + wid * 33 + s];
            tw[0 * TROW] = v.x; tw[1 * TROW] = v.y;
            tw[2 * TROW] = v.z; tw[3 * TROW] = v.w;
        }
        if (lane < 4) {   // s = 32
            const int i = s_sidx[wid][32];
            const float4 v = ftb[(size_t)i * 16];   // c4 = lane
            float* tw = &s_tile[(lane * 4) * TROW + wid * 33 + 32];
            tw[0 * TROW] = v.x; tw[1 * TROW] = v.y;
            tw[2 * TROW] = v.z; tw[3 * TROW] = v.w;
        }
        __syncthreads();

        for (int e = tid; e < PCH * 33; e += FW * 32) {
            const int ch = (e * 993) >> 15;        // e / 33
            const int q  = e - ch * 33;
            const float4 v = *(const float4*)&s_tile[ch * TROW + q * 4];
            *(float4*)(outb0 + (size_t)(6 + p * PCH + ch) * chstr + q * 4) = v;
        }
        __syncthreads();
    }
}

// ---------------------------------------------------------------------------
extern "C" void kernel_launch(void* const* d_in, const int* in_sizes, int n_in,
                              void* d_out, int out_size) {
    const float* xyz      = (const float*)d_in[0];   // (B, N, 3)
    const float* new_xyz  = (const float*)d_in[1];   // (B, NPOINT, 3)
    const float* features = (const float*)d_in[2];   // (B, C, N)
    const int*   fps_idx  = (const int*)d_in[3];     // (B, NPOINT)
    float* out = (float*)d_out;

    pre_kernel<<<GB_BLOCKS + FT_BLOCKS, 1024>>>(features, xyz);

    // bq launch with programmatic dependent launch: dispatches while pre
    // drains; cudaGridDependencySynchronize() inside gates the grid reads.
    {
        cudaLaunchConfig_t cfg = {};
        cfg.gridDim  = dim3((BB * NPOINT) / FW);   // 2048
        cfg.blockDim = dim3(FW * 32);
        cudaLaunchAttribute attr[1];
        attr[0].id = cudaLaunchAttributeProgrammaticStreamSerialization;
        attr[0].val.programmaticStreamSerializationAllowed = 1;
        cfg.attrs = attr;
        cfg.numAttrs = 1;
        cudaLaunchKernelEx(&cfg, bq_gather_kernel, new_xyz, fps_idx,
                           (float*)out);
    }
}